// round 4
// baseline (speedup 1.0000x reference)
#include <cuda_runtime.h>
#include <math.h>

#define Bn 4
#define Tn 2048
#define Cn 1024
#define Hn 16
#define Dn 64
#define NT (Bn * Tn)
#define C3 (3 * Cn)

__device__ float g_q[(size_t)Bn * Hn * Tn * Dn];
__device__ float g_k[(size_t)Bn * Hn * Tn * Dn];
__device__ float g_v[(size_t)Bn * Hn * Tn * Dn];
__device__ float g_y[(size_t)NT * Cn];

// ---------------- QKV GEMM: x @ w_qkv + b_qkv -> scatter [B,H,T,D] ----------
__global__ __launch_bounds__(256) void qkv_gemm(const float* __restrict__ A,
                                                const float* __restrict__ W,
                                                const float* __restrict__ bias) {
    __shared__ float As[8][128];
    __shared__ float Bs[8][128];

    const int tid = threadIdx.x;
    const int tx = tid & 15;
    const int ty = tid >> 4;
    const int rowBase = blockIdx.y * 128;
    const int colBase = blockIdx.x * 128;

    const int aRow  = tid >> 1;
    const int aCol4 = (tid & 1) * 4;
    const int bRow  = tid >> 5;
    const int bCol4 = (tid & 31) * 4;

    float acc[8][8] = {};

    for (int k0 = 0; k0 < Cn; k0 += 8) {
        float4 av = *(const float4*)&A[(size_t)(rowBase + aRow) * Cn + k0 + aCol4];
        As[aCol4 + 0][aRow] = av.x;
        As[aCol4 + 1][aRow] = av.y;
        As[aCol4 + 2][aRow] = av.z;
        As[aCol4 + 3][aRow] = av.w;
        float4 bv = *(const float4*)&W[(size_t)(k0 + bRow) * C3 + colBase + bCol4];
        *(float4*)&Bs[bRow][bCol4] = bv;
        __syncthreads();

#pragma unroll
        for (int kk = 0; kk < 8; kk++) {
            float ar[8], br[8];
            *(float4*)&ar[0] = *(const float4*)&As[kk][ty * 8];
            *(float4*)&ar[4] = *(const float4*)&As[kk][ty * 8 + 4];
            *(float4*)&br[0] = *(const float4*)&Bs[kk][tx * 8];
            *(float4*)&br[4] = *(const float4*)&Bs[kk][tx * 8 + 4];
#pragma unroll
            for (int i = 0; i < 8; i++)
#pragma unroll
                for (int j = 0; j < 8; j++)
                    acc[i][j] = fmaf(ar[i], br[j], acc[i][j]);
        }
        __syncthreads();
    }

#pragma unroll
    for (int i = 0; i < 8; i++) {
        const int m = rowBase + ty * 8 + i;
        const int b = m / Tn;
        const int t = m % Tn;
#pragma unroll
        for (int j = 0; j < 8; j++) {
            const int n = colBase + tx * 8 + j;
            const float v = acc[i][j] + bias[n];
            const int which = n / Cn;
            const int cc = n - which * Cn;
            const int h = cc >> 6;
            const int d = cc & 63;
            float* dst = (which == 0) ? g_q : (which == 1) ? g_k : g_v;
            dst[(((size_t)b * Hn + h) * Tn + t) * Dn + d] = v;
        }
    }
}

// ---------------- Flash attention (causal), Br=Bc=64 ------------------------
#define LDP 68
#define ATTN_SMEM ((4 * 64 * LDP + 3 * 64) * 4)

__global__ __launch_bounds__(256) void attn_kernel() {
    extern __shared__ float sm[];
    float* Qs = sm;                   // [d][row]
    float* Ks = Qs + 64 * LDP;        // [d][col]
    float* Vs = Ks + 64 * LDP;        // [kk][col]
    float* Ps = Vs + 64 * LDP;        // [kk][row] = S^T / P^T
    float* m_s = Ps + 64 * LDP;
    float* l_s = m_s + 64;
    float* al_s = l_s + 64;

    const int qt = blockIdx.x;
    const int bh = blockIdx.y;
    const int b = bh >> 4;
    const int h = bh & 15;

    const int tid = threadIdx.x;
    const int tx = tid & 15, ty = tid >> 4;
    const int r0 = ty * 4, c0 = tx * 4;

    const float* qg = g_q + ((size_t)bh * Tn + qt * 64) * Dn;
    const float scale = 0.125f;

    for (int i = tid; i < 64 * 64; i += 256) {
        int r = i >> 6, d = i & 63;
        Qs[d * LDP + r] = qg[i] * scale;
    }
    if (tid < 64) { m_s[tid] = -INFINITY; l_s[tid] = 0.0f; }

    float o[4][4] = {};
    __syncthreads();

    for (int j = 0; j <= qt; j++) {
        const float* kg = g_k + ((size_t)bh * Tn + j * 64) * Dn;
        const float* vg = g_v + ((size_t)bh * Tn + j * 64) * Dn;
        for (int i = tid; i < 64 * 64; i += 256) {
            int r = i >> 6, d = i & 63;
            Ks[d * LDP + r] = kg[i];      // transposed to d-major
            Vs[r * LDP + d] = vg[i];      // natural k-major
        }
        __syncthreads();

        float s[4][4] = {};
#pragma unroll 8
        for (int d = 0; d < 64; d++) {
            float4 qv = *(const float4*)&Qs[d * LDP + r0];
            float4 kv = *(const float4*)&Ks[d * LDP + c0];
            s[0][0] = fmaf(qv.x, kv.x, s[0][0]); s[0][1] = fmaf(qv.x, kv.y, s[0][1]);
            s[0][2] = fmaf(qv.x, kv.z, s[0][2]); s[0][3] = fmaf(qv.x, kv.w, s[0][3]);
            s[1][0] = fmaf(qv.y, kv.x, s[1][0]); s[1][1] = fmaf(qv.y, kv.y, s[1][1]);
            s[1][2] = fmaf(qv.y, kv.z, s[1][2]); s[1][3] = fmaf(qv.y, kv.w, s[1][3]);
            s[2][0] = fmaf(qv.z, kv.x, s[2][0]); s[2][1] = fmaf(qv.z, kv.y, s[2][1]);
            s[2][2] = fmaf(qv.z, kv.z, s[2][2]); s[2][3] = fmaf(qv.z, kv.w, s[2][3]);
            s[3][0] = fmaf(qv.w, kv.x, s[3][0]); s[3][1] = fmaf(qv.w, kv.y, s[3][1]);
            s[3][2] = fmaf(qv.w, kv.z, s[3][2]); s[3][3] = fmaf(qv.w, kv.w, s[3][3]);
        }
#pragma unroll
        for (int jj = 0; jj < 4; jj++)
            *(float4*)&Ps[(c0 + jj) * LDP + r0] =
                make_float4(s[0][jj], s[1][jj], s[2][jj], s[3][jj]);
        __syncthreads();

        if (tid < 64) {
            const int row = tid;
            const int kmax = (j == qt) ? row : 63;
            float mold = m_s[row];
            float mx = mold;
            for (int kk = 0; kk <= kmax; kk++)
                mx = fmaxf(mx, Ps[kk * LDP + row]);
            float alpha = __expf(mold - mx);
            float l = l_s[row] * alpha;
            for (int kk = 0; kk < 64; kk++) {
                float p = (kk <= kmax) ? __expf(Ps[kk * LDP + row] - mx) : 0.0f;
                Ps[kk * LDP + row] = p;
                l += p;
            }
            m_s[row] = mx;
            l_s[row] = l;
            al_s[row] = alpha;
        }
        __syncthreads();

        const float a0 = al_s[r0], a1 = al_s[r0 + 1], a2 = al_s[r0 + 2], a3 = al_s[r0 + 3];
#pragma unroll
        for (int jj = 0; jj < 4; jj++) {
            o[0][jj] *= a0; o[1][jj] *= a1; o[2][jj] *= a2; o[3][jj] *= a3;
        }
#pragma unroll 8
        for (int kk = 0; kk < 64; kk++) {
            float4 pv = *(const float4*)&Ps[kk * LDP + r0];
            float4 vv = *(const float4*)&Vs[kk * LDP + c0];
            o[0][0] = fmaf(pv.x, vv.x, o[0][0]); o[0][1] = fmaf(pv.x, vv.y, o[0][1]);
            o[0][2] = fmaf(pv.x, vv.z, o[0][2]); o[0][3] = fmaf(pv.x, vv.w, o[0][3]);
            o[1][0] = fmaf(pv.y, vv.x, o[1][0]); o[1][1] = fmaf(pv.y, vv.y, o[1][1]);
            o[1][2] = fmaf(pv.y, vv.z, o[1][2]); o[1][3] = fmaf(pv.y, vv.w, o[1][3]);
            o[2][0] = fmaf(pv.z, vv.x, o[2][0]); o[2][1] = fmaf(pv.z, vv.y, o[2][1]);
            o[2][2] = fmaf(pv.z, vv.z, o[2][2]); o[2][3] = fmaf(pv.z, vv.w, o[2][3]);
            o[3][0] = fmaf(pv.w, vv.x, o[3][0]); o[3][1] = fmaf(pv.w, vv.y, o[3][1]);
            o[3][2] = fmaf(pv.w, vv.z, o[3][2]); o[3][3] = fmaf(pv.w, vv.w, o[3][3]);
        }
        __syncthreads();
    }

#pragma unroll
    for (int ii = 0; ii < 4; ii++) {
        const float inv = 1.0f / l_s[r0 + ii];
        const int t = qt * 64 + r0 + ii;
        float4 ov = make_float4(o[ii][0] * inv, o[ii][1] * inv,
                                o[ii][2] * inv, o[ii][3] * inv);
        *(float4*)&g_y[((size_t)b * Tn + t) * Cn + h * 64 + c0] = ov;
    }
}

// ---------------- Output projection: g_y @ w_proj + b_proj ------------------
__global__ __launch_bounds__(256) void proj_gemm(const float* __restrict__ W,
                                                 const float* __restrict__ bias,
                                                 float* __restrict__ out) {
    __shared__ float As[8][128];
    __shared__ float Bs[8][128];

    const int tid = threadIdx.x;
    const int tx = tid & 15, ty = tid >> 4;
    const int rowBase = blockIdx.y * 128;
    const int colBase = blockIdx.x * 128;

    const int aRow  = tid >> 1;
    const int aCol4 = (tid & 1) * 4;
    const int bRow  = tid >> 5;
    const int bCol4 = (tid & 31) * 4;

    float acc[8][8] = {};

    for (int k0 = 0; k0 < Cn; k0 += 8) {
        float4 av = *(const float4*)&g_y[(size_t)(rowBase + aRow) * Cn + k0 + aCol4];
        As[aCol4 + 0][aRow] = av.x;
        As[aCol4 + 1][aRow] = av.y;
        As[aCol4 + 2][aRow] = av.z;
        As[aCol4 + 3][aRow] = av.w;
        float4 bv = *(const float4*)&W[(size_t)(k0 + bRow) * Cn + colBase + bCol4];
        *(float4*)&Bs[bRow][bCol4] = bv;
        __syncthreads();

#pragma unroll
        for (int kk = 0; kk < 8; kk++) {
            float ar[8], br[8];
            *(float4*)&ar[0] = *(const float4*)&As[kk][ty * 8];
            *(float4*)&ar[4] = *(const float4*)&As[kk][ty * 8 + 4];
            *(float4*)&br[0] = *(const float4*)&Bs[kk][tx * 8];
            *(float4*)&br[4] = *(const float4*)&Bs[kk][tx * 8 + 4];
#pragma unroll
            for (int i = 0; i < 8; i++)
#pragma unroll
                for (int j = 0; j < 8; j++)
                    acc[i][j] = fmaf(ar[i], br[j], acc[i][j]);
        }
        __syncthreads();
    }

#pragma unroll
    for (int i = 0; i < 8; i++) {
        const int m = rowBase + ty * 8 + i;
#pragma unroll
        for (int j4 = 0; j4 < 8; j4 += 4) {
            const int n = colBase + tx * 8 + j4;
            float4 ov = make_float4(acc[i][j4 + 0] + bias[n + 0],
                                    acc[i][j4 + 1] + bias[n + 1],
                                    acc[i][j4 + 2] + bias[n + 2],
                                    acc[i][j4 + 3] + bias[n + 3]);
            *(float4*)&out[(size_t)m * Cn + n] = ov;
        }
    }
}

extern "C" void kernel_launch(void* const* d_in, const int* in_sizes, int n_in,
                              void* d_out, int out_size) {
    const float* x      = (const float*)d_in[0];
    const float* w_qkv  = (const float*)d_in[1];
    const float* b_qkv  = (const float*)d_in[2];
    const float* w_proj = (const float*)d_in[3];
    const float* b_proj = (const float*)d_in[4];
    float* out = (float*)d_out;

    cudaFuncSetAttribute(attn_kernel,
                         cudaFuncAttributeMaxDynamicSharedMemorySize, ATTN_SMEM);

    qkv_gemm<<<dim3(C3 / 128, NT / 128), 256>>>(x, w_qkv, b_qkv);
    attn_kernel<<<dim3(Tn / 64, Bn * Hn), 256, ATTN_SMEM>>>();
    proj_gemm<<<dim3(Cn / 128, NT / 128), 256>>>(w_proj, b_proj, out);
}

// round 6
// speedup vs baseline: 1.6100x; 1.6100x over previous
#include <cuda_runtime.h>
#include <math.h>
#include <stdint.h>

#define Bn 4
#define Tn 2048
#define Cn 1024
#define Hn 16
#define Dn 64
#define NT (Bn * Tn)
#define C3 (3 * Cn)

__device__ float g_q[(size_t)Bn * Hn * Tn * Dn];
__device__ float g_k[(size_t)Bn * Hn * Tn * Dn];
__device__ float g_v[(size_t)Bn * Hn * Tn * Dn];
__device__ float g_y[(size_t)NT * Cn];

// ---------------------------------------------------------------------------
// tf32 helpers
// ---------------------------------------------------------------------------
__device__ __forceinline__ float f2tf(float x) {
    float y;
    asm("cvt.rna.tf32.f32 %0, %1;" : "=f"(y) : "f"(x));
    return y;
}

__device__ __forceinline__ void mma8(float d[4], const uint32_t a[4],
                                     const uint32_t b[2], const float c[4]) {
    asm volatile(
        "mma.sync.aligned.m16n8k8.row.col.f32.tf32.tf32.f32 "
        "{%0,%1,%2,%3}, {%4,%5,%6,%7}, {%8,%9}, {%10,%11,%12,%13};"
        : "=f"(d[0]), "=f"(d[1]), "=f"(d[2]), "=f"(d[3])
        : "r"(a[0]), "r"(a[1]), "r"(a[2]), "r"(a[3]),
          "r"(b[0]), "r"(b[1]),
          "f"(c[0]), "f"(c[1]), "f"(c[2]), "f"(c[3]));
}

// ---------------------------------------------------------------------------
// tf32 tensor-core GEMM: out[M,N] = A[M,K] @ W[K,N] + bias
// BM=128 BN=128 BK=16, 8 warps (4 along M x 2 along N), warp tile 32x64.
// MODE 0: QKV — A from kernel arg (harness input x), scatter to g_q/g_k/g_v.
// MODE 1: proj — A is the device-global g_y (resolved IN DEVICE CODE; a
//         __device__ symbol must never be passed as a host-side kernel arg,
//         which is what crashed Round 5), writes out[m*Cn+n].
// ---------------------------------------------------------------------------
template <int MODE>
__global__ __launch_bounds__(256, 2) void tf32_gemm(const float* __restrict__ Ain,
                                                    const float* __restrict__ Wm,
                                                    const float* __restrict__ bias,
                                                    float* __restrict__ out,
                                                    int ldb) {
    const float* __restrict__ A = (MODE == 1) ? (const float*)g_y : Ain;

    __shared__ float As[128][20];   // [m][k]
    __shared__ float Bs[16][136];   // [k][n]

    const int tid = threadIdx.x;
    const int lane = tid & 31;
    const int warp = tid >> 5;
    const int warpM = warp & 3;     // 0..3 -> 32-row slab
    const int warpN = warp >> 2;    // 0..1 -> 64-col slab
    const int gid = lane >> 2;      // groupID 0..7
    const int qid = lane & 3;       // thread-in-group 0..3

    const int rowBase = blockIdx.y * 128;
    const int colBase = blockIdx.x * 128;

    // Loaders: A tile 128x16 (2 float4/thread), B tile 16x128 (2 float4/thread)
    const int aRow = tid >> 1;
    const int aCol = (tid & 1) * 8;
    const int bRow = tid >> 4;
    const int bCol = (tid & 15) * 8;

    float acc[2][8][4] = {};

    for (int k0 = 0; k0 < Cn; k0 += 16) {
        float4 av0 = *(const float4*)&A[(size_t)(rowBase + aRow) * Cn + k0 + aCol];
        float4 av1 = *(const float4*)&A[(size_t)(rowBase + aRow) * Cn + k0 + aCol + 4];
        *(float4*)&As[aRow][aCol] =
            make_float4(f2tf(av0.x), f2tf(av0.y), f2tf(av0.z), f2tf(av0.w));
        *(float4*)&As[aRow][aCol + 4] =
            make_float4(f2tf(av1.x), f2tf(av1.y), f2tf(av1.z), f2tf(av1.w));

        float4 bv0 = *(const float4*)&Wm[(size_t)(k0 + bRow) * ldb + colBase + bCol];
        float4 bv1 = *(const float4*)&Wm[(size_t)(k0 + bRow) * ldb + colBase + bCol + 4];
        *(float4*)&Bs[bRow][bCol] =
            make_float4(f2tf(bv0.x), f2tf(bv0.y), f2tf(bv0.z), f2tf(bv0.w));
        *(float4*)&Bs[bRow][bCol + 4] =
            make_float4(f2tf(bv1.x), f2tf(bv1.y), f2tf(bv1.z), f2tf(bv1.w));
        __syncthreads();

#pragma unroll
        for (int ks = 0; ks < 16; ks += 8) {
            uint32_t afr[2][4];
            uint32_t bfr[8][2];
#pragma unroll
            for (int mt = 0; mt < 2; mt++) {
                const int r = warpM * 32 + mt * 16 + gid;
                afr[mt][0] = __float_as_uint(As[r][ks + qid]);
                afr[mt][1] = __float_as_uint(As[r + 8][ks + qid]);
                afr[mt][2] = __float_as_uint(As[r][ks + qid + 4]);
                afr[mt][3] = __float_as_uint(As[r + 8][ks + qid + 4]);
            }
#pragma unroll
            for (int nt = 0; nt < 8; nt++) {
                const int c = warpN * 64 + nt * 8 + gid;
                bfr[nt][0] = __float_as_uint(Bs[ks + qid][c]);
                bfr[nt][1] = __float_as_uint(Bs[ks + qid + 4][c]);
            }
#pragma unroll
            for (int mt = 0; mt < 2; mt++)
#pragma unroll
                for (int nt = 0; nt < 8; nt++)
                    mma8(acc[mt][nt], afr[mt], bfr[nt], acc[mt][nt]);
        }
        __syncthreads();
    }

    // Epilogue. Fragment c: {c0,c1} row gid, cols qid*2/qid*2+1; {c2,c3} row gid+8.
#pragma unroll
    for (int mt = 0; mt < 2; mt++) {
#pragma unroll
        for (int ih = 0; ih < 2; ih++) {
            const int m = rowBase + warpM * 32 + mt * 16 + gid + ih * 8;
#pragma unroll
            for (int nt = 0; nt < 8; nt++) {
                const int n = colBase + warpN * 64 + nt * 8 + qid * 2;
                const float v0 = acc[mt][nt][ih * 2 + 0] + bias[n];
                const float v1 = acc[mt][nt][ih * 2 + 1] + bias[n + 1];
                if (MODE == 1) {
                    *(float2*)&out[(size_t)m * Cn + n] = make_float2(v0, v1);
                } else {
                    const int which = n >> 10;       // 0=q 1=k 2=v
                    const int cc = n & 1023;
                    const int h = cc >> 6;
                    const int d = cc & 63;           // d,d+1 same head
                    const int b = m >> 11;
                    const int t = m & 2047;
                    float* dst = (which == 0) ? g_q : (which == 1) ? g_k : g_v;
                    *(float2*)&dst[(((size_t)b * Hn + h) * Tn + t) * Dn + d] =
                        make_float2(v0, v1);
                }
            }
        }
    }
}

// ---------------- Flash attention (causal), Br=Bc=64 — unchanged ------------
#define LDP 68
#define ATTN_SMEM ((4 * 64 * LDP + 3 * 64) * 4)

__global__ __launch_bounds__(256) void attn_kernel() {
    extern __shared__ float sm[];
    float* Qs = sm;                   // [d][row]
    float* Ks = Qs + 64 * LDP;        // [d][col]
    float* Vs = Ks + 64 * LDP;        // [kk][col]
    float* Ps = Vs + 64 * LDP;        // [kk][row] = S^T / P^T
    float* m_s = Ps + 64 * LDP;
    float* l_s = m_s + 64;
    float* al_s = l_s + 64;

    const int qt = blockIdx.x;
    const int bh = blockIdx.y;
    const int b = bh >> 4;
    const int h = bh & 15;

    const int tid = threadIdx.x;
    const int tx = tid & 15, ty = tid >> 4;
    const int r0 = ty * 4, c0 = tx * 4;

    const float* qg = g_q + ((size_t)bh * Tn + qt * 64) * Dn;
    const float scale = 0.125f;

    for (int i = tid; i < 64 * 64; i += 256) {
        int r = i >> 6, d = i & 63;
        Qs[d * LDP + r] = qg[i] * scale;
    }
    if (tid < 64) { m_s[tid] = -INFINITY; l_s[tid] = 0.0f; }

    float o[4][4] = {};
    __syncthreads();

    for (int j = 0; j <= qt; j++) {
        const float* kg = g_k + ((size_t)bh * Tn + j * 64) * Dn;
        const float* vg = g_v + ((size_t)bh * Tn + j * 64) * Dn;
        for (int i = tid; i < 64 * 64; i += 256) {
            int r = i >> 6, d = i & 63;
            Ks[d * LDP + r] = kg[i];
            Vs[r * LDP + d] = vg[i];
        }
        __syncthreads();

        float s[4][4] = {};
#pragma unroll 8
        for (int d = 0; d < 64; d++) {
            float4 qv = *(const float4*)&Qs[d * LDP + r0];
            float4 kv = *(const float4*)&Ks[d * LDP + c0];
            s[0][0] = fmaf(qv.x, kv.x, s[0][0]); s[0][1] = fmaf(qv.x, kv.y, s[0][1]);
            s[0][2] = fmaf(qv.x, kv.z, s[0][2]); s[0][3] = fmaf(qv.x, kv.w, s[0][3]);
            s[1][0] = fmaf(qv.y, kv.x, s[1][0]); s[1][1] = fmaf(qv.y, kv.y, s[1][1]);
            s[1][2] = fmaf(qv.y, kv.z, s[1][2]); s[1][3] = fmaf(qv.y, kv.w, s[1][3]);
            s[2][0] = fmaf(qv.z, kv.x, s[2][0]); s[2][1] = fmaf(qv.z, kv.y, s[2][1]);
            s[2][2] = fmaf(qv.z, kv.z, s[2][2]); s[2][3] = fmaf(qv.z, kv.w, s[2][3]);
            s[3][0] = fmaf(qv.w, kv.x, s[3][0]); s[3][1] = fmaf(qv.w, kv.y, s[3][1]);
            s[3][2] = fmaf(qv.w, kv.z, s[3][2]); s[3][3] = fmaf(qv.w, kv.w, s[3][3]);
        }
#pragma unroll
        for (int jj = 0; jj < 4; jj++)
            *(float4*)&Ps[(c0 + jj) * LDP + r0] =
                make_float4(s[0][jj], s[1][jj], s[2][jj], s[3][jj]);
        __syncthreads();

        if (tid < 64) {
            const int row = tid;
            const int kmax = (j == qt) ? row : 63;
            float mold = m_s[row];
            float mx = mold;
            for (int kk = 0; kk <= kmax; kk++)
                mx = fmaxf(mx, Ps[kk * LDP + row]);
            float alpha = __expf(mold - mx);
            float l = l_s[row] * alpha;
            for (int kk = 0; kk < 64; kk++) {
                float p = (kk <= kmax) ? __expf(Ps[kk * LDP + row] - mx) : 0.0f;
                Ps[kk * LDP + row] = p;
                l += p;
            }
            m_s[row] = mx;
            l_s[row] = l;
            al_s[row] = alpha;
        }
        __syncthreads();

        const float a0 = al_s[r0], a1 = al_s[r0 + 1], a2 = al_s[r0 + 2], a3 = al_s[r0 + 3];
#pragma unroll
        for (int jj = 0; jj < 4; jj++) {
            o[0][jj] *= a0; o[1][jj] *= a1; o[2][jj] *= a2; o[3][jj] *= a3;
        }
#pragma unroll 8
        for (int kk = 0; kk < 64; kk++) {
            float4 pv = *(const float4*)&Ps[kk * LDP + r0];
            float4 vv = *(const float4*)&Vs[kk * LDP + c0];
            o[0][0] = fmaf(pv.x, vv.x, o[0][0]); o[0][1] = fmaf(pv.x, vv.y, o[0][1]);
            o[0][2] = fmaf(pv.x, vv.z, o[0][2]); o[0][3] = fmaf(pv.x, vv.w, o[0][3]);
            o[1][0] = fmaf(pv.y, vv.x, o[1][0]); o[1][1] = fmaf(pv.y, vv.y, o[1][1]);
            o[1][2] = fmaf(pv.y, vv.z, o[1][2]); o[1][3] = fmaf(pv.y, vv.w, o[1][3]);
            o[2][0] = fmaf(pv.z, vv.x, o[2][0]); o[2][1] = fmaf(pv.z, vv.y, o[2][1]);
            o[2][2] = fmaf(pv.z, vv.z, o[2][2]); o[2][3] = fmaf(pv.z, vv.w, o[2][3]);
            o[3][0] = fmaf(pv.w, vv.x, o[3][0]); o[3][1] = fmaf(pv.w, vv.y, o[3][1]);
            o[3][2] = fmaf(pv.w, vv.z, o[3][2]); o[3][3] = fmaf(pv.w, vv.w, o[3][3]);
        }
        __syncthreads();
    }

#pragma unroll
    for (int ii = 0; ii < 4; ii++) {
        const float inv = 1.0f / l_s[r0 + ii];
        const int t = qt * 64 + r0 + ii;
        float4 ov = make_float4(o[ii][0] * inv, o[ii][1] * inv,
                                o[ii][2] * inv, o[ii][3] * inv);
        *(float4*)&g_y[((size_t)b * Tn + t) * Cn + h * 64 + c0] = ov;
    }
}

// ---------------------------------------------------------------------------
extern "C" void kernel_launch(void* const* d_in, const int* in_sizes, int n_in,
                              void* d_out, int out_size) {
    const float* x      = (const float*)d_in[0];
    const float* w_qkv  = (const float*)d_in[1];
    const float* b_qkv  = (const float*)d_in[2];
    const float* w_proj = (const float*)d_in[3];
    const float* b_proj = (const float*)d_in[4];
    float* out = (float*)d_out;

    cudaFuncSetAttribute(attn_kernel,
                         cudaFuncAttributeMaxDynamicSharedMemorySize, ATTN_SMEM);

    // QKV: [8192,1024] @ [1024,3072]  (MODE 0 scatters into g_q/g_k/g_v)
    tf32_gemm<0><<<dim3(C3 / 128, NT / 128), 256>>>(x, w_qkv, b_qkv, nullptr, C3);
    attn_kernel<<<dim3(Tn / 64, Bn * Hn), 256, ATTN_SMEM>>>();
    // proj: A = g_y resolved inside the kernel (MODE 1); arg is ignored.
    tf32_gemm<1><<<dim3(Cn / 128, NT / 128), 256>>>(nullptr, w_proj, b_proj, out, Cn);
}

// round 7
// speedup vs baseline: 2.8679x; 1.7813x over previous
#include <cuda_runtime.h>
#include <math.h>
#include <stdint.h>

#define Bn 4
#define Tn 2048
#define Cn 1024
#define Hn 16
#define Dn 64
#define NT (Bn * Tn)
#define C3 (3 * Cn)

__device__ float g_q[(size_t)Bn * Hn * Tn * Dn];
__device__ float g_k[(size_t)Bn * Hn * Tn * Dn];
__device__ float g_v[(size_t)Bn * Hn * Tn * Dn];
__device__ float g_y[(size_t)NT * Cn];

// ---------------------------------------------------------------------------
// helpers
// ---------------------------------------------------------------------------
__device__ __forceinline__ float f2tf(float x) {
    float y;
    asm("cvt.rna.tf32.f32 %0, %1;" : "=f"(y) : "f"(x));
    return y;
}

__device__ __forceinline__ float ex2(float x) {
    float y;
    asm("ex2.approx.f32 %0, %1;" : "=f"(y) : "f"(x));
    return y;
}

__device__ __forceinline__ void mma8(float d[4], const uint32_t a[4],
                                     const uint32_t b[2], const float c[4]) {
    asm volatile(
        "mma.sync.aligned.m16n8k8.row.col.f32.tf32.tf32.f32 "
        "{%0,%1,%2,%3}, {%4,%5,%6,%7}, {%8,%9}, {%10,%11,%12,%13};"
        : "=f"(d[0]), "=f"(d[1]), "=f"(d[2]), "=f"(d[3])
        : "r"(a[0]), "r"(a[1]), "r"(a[2]), "r"(a[3]),
          "r"(b[0]), "r"(b[1]),
          "f"(c[0]), "f"(c[1]), "f"(c[2]), "f"(c[3]));
}

// ---------------------------------------------------------------------------
// tf32 tensor-core GEMM (unchanged from R6 passing version)
// ---------------------------------------------------------------------------
template <int MODE>
__global__ __launch_bounds__(256, 2) void tf32_gemm(const float* __restrict__ Ain,
                                                    const float* __restrict__ Wm,
                                                    const float* __restrict__ bias,
                                                    float* __restrict__ out,
                                                    int ldb) {
    const float* __restrict__ A = (MODE == 1) ? (const float*)g_y : Ain;

    __shared__ float As[128][20];   // [m][k]
    __shared__ float Bs[16][136];   // [k][n]

    const int tid = threadIdx.x;
    const int lane = tid & 31;
    const int warp = tid >> 5;
    const int warpM = warp & 3;
    const int warpN = warp >> 2;
    const int gid = lane >> 2;
    const int qid = lane & 3;

    const int rowBase = blockIdx.y * 128;
    const int colBase = blockIdx.x * 128;

    const int aRow = tid >> 1;
    const int aCol = (tid & 1) * 8;
    const int bRow = tid >> 4;
    const int bCol = (tid & 15) * 8;

    float acc[2][8][4] = {};

    for (int k0 = 0; k0 < Cn; k0 += 16) {
        float4 av0 = *(const float4*)&A[(size_t)(rowBase + aRow) * Cn + k0 + aCol];
        float4 av1 = *(const float4*)&A[(size_t)(rowBase + aRow) * Cn + k0 + aCol + 4];
        *(float4*)&As[aRow][aCol] =
            make_float4(f2tf(av0.x), f2tf(av0.y), f2tf(av0.z), f2tf(av0.w));
        *(float4*)&As[aRow][aCol + 4] =
            make_float4(f2tf(av1.x), f2tf(av1.y), f2tf(av1.z), f2tf(av1.w));

        float4 bv0 = *(const float4*)&Wm[(size_t)(k0 + bRow) * ldb + colBase + bCol];
        float4 bv1 = *(const float4*)&Wm[(size_t)(k0 + bRow) * ldb + colBase + bCol + 4];
        *(float4*)&Bs[bRow][bCol] =
            make_float4(f2tf(bv0.x), f2tf(bv0.y), f2tf(bv0.z), f2tf(bv0.w));
        *(float4*)&Bs[bRow][bCol + 4] =
            make_float4(f2tf(bv1.x), f2tf(bv1.y), f2tf(bv1.z), f2tf(bv1.w));
        __syncthreads();

#pragma unroll
        for (int ks = 0; ks < 16; ks += 8) {
            uint32_t afr[2][4];
            uint32_t bfr[8][2];
#pragma unroll
            for (int mt = 0; mt < 2; mt++) {
                const int r = warpM * 32 + mt * 16 + gid;
                afr[mt][0] = __float_as_uint(As[r][ks + qid]);
                afr[mt][1] = __float_as_uint(As[r + 8][ks + qid]);
                afr[mt][2] = __float_as_uint(As[r][ks + qid + 4]);
                afr[mt][3] = __float_as_uint(As[r + 8][ks + qid + 4]);
            }
#pragma unroll
            for (int nt = 0; nt < 8; nt++) {
                const int c = warpN * 64 + nt * 8 + gid;
                bfr[nt][0] = __float_as_uint(Bs[ks + qid][c]);
                bfr[nt][1] = __float_as_uint(Bs[ks + qid + 4][c]);
            }
#pragma unroll
            for (int mt = 0; mt < 2; mt++)
#pragma unroll
                for (int nt = 0; nt < 8; nt++)
                    mma8(acc[mt][nt], afr[mt], bfr[nt], acc[mt][nt]);
        }
        __syncthreads();
    }

#pragma unroll
    for (int mt = 0; mt < 2; mt++) {
#pragma unroll
        for (int ih = 0; ih < 2; ih++) {
            const int m = rowBase + warpM * 32 + mt * 16 + gid + ih * 8;
#pragma unroll
            for (int nt = 0; nt < 8; nt++) {
                const int n = colBase + warpN * 64 + nt * 8 + qid * 2;
                const float v0 = acc[mt][nt][ih * 2 + 0] + bias[n];
                const float v1 = acc[mt][nt][ih * 2 + 1] + bias[n + 1];
                if (MODE == 1) {
                    *(float2*)&out[(size_t)m * Cn + n] = make_float2(v0, v1);
                } else {
                    const int which = n >> 10;
                    const int cc = n & 1023;
                    const int h = cc >> 6;
                    const int d = cc & 63;
                    const int b = m >> 11;
                    const int t = m & 2047;
                    float* dst = (which == 0) ? g_q : (which == 1) ? g_k : g_v;
                    *(float2*)&dst[(((size_t)b * Hn + h) * Tn + t) * Dn + d] =
                        make_float2(v0, v1);
                }
            }
        }
    }
}

// ---------------------------------------------------------------------------
// Tensor-core flash attention (causal). Br=Bc=64, 4 warps x 16 rows.
// Q fragments resident in registers; K/V natural row-major smem stride 72
// (conflict-free for all fragment patterns); softmax in registers with quad
// shuffles; P via per-warp smem patch to convert C-layout -> A-layout.
// ---------------------------------------------------------------------------
#define LKV 72
#define ATTN_SMEM ((2 * 64 * LKV + 4 * 16 * LKV) * 4)

__global__ __launch_bounds__(128, 3) void attn_tc() {
    extern __shared__ float smf[];
    float* Kn = smf;                    // [kv][d]  stride LKV
    float* Vs = smf + 64 * LKV;         // [kv][d]  stride LKV
    float* Pw = smf + 2 * 64 * LKV;     // per-warp [16][LKV]

    const int qt = blockIdx.x;
    const int bh = blockIdx.y;
    const int b = bh >> 4;
    const int h = bh & 15;

    const int tid = threadIdx.x;
    const int w = tid >> 5;
    const int lane = tid & 31;
    const int g = lane >> 2;      // groupID 0..7
    const int q = lane & 3;       // quad thread 0..3

    // Q fragments: rows w*16+g, w*16+g+8; scale folds 1/sqrt(D) and log2(e)
    const float qscale = 0.125f * 1.44269504f;
    const float* qg = g_q + ((size_t)bh * Tn + qt * 64 + w * 16) * Dn;
    uint32_t aQ[8][4];
#pragma unroll
    for (int ks = 0; ks < 8; ks++) {
        aQ[ks][0] = __float_as_uint(f2tf(qg[g * Dn + ks * 8 + q] * qscale));
        aQ[ks][1] = __float_as_uint(f2tf(qg[(g + 8) * Dn + ks * 8 + q] * qscale));
        aQ[ks][2] = __float_as_uint(f2tf(qg[g * Dn + ks * 8 + q + 4] * qscale));
        aQ[ks][3] = __float_as_uint(f2tf(qg[(g + 8) * Dn + ks * 8 + q + 4] * qscale));
    }

    float o[8][4] = {};
    float mrow[2] = {-INFINITY, -INFINITY};
    float lrow[2] = {0.0f, 0.0f};

    const float* kg0 = g_k + (size_t)bh * Tn * Dn;
    const float* vg0 = g_v + (size_t)bh * Tn * Dn;
    float* Pme = Pw + w * 16 * LKV;

    for (int j = 0; j <= qt; j++) {
        __syncthreads();   // all warps done with previous K/V tile
        const float* kg = kg0 + (size_t)j * 64 * Dn;
        const float* vg = vg0 + (size_t)j * 64 * Dn;
        for (int i = tid; i < 64 * 16; i += 128) {
            const int r = i >> 4;
            const int c = (i & 15) * 4;
            float4 k4 = *(const float4*)&kg[r * Dn + c];
            *(float4*)&Kn[r * LKV + c] =
                make_float4(f2tf(k4.x), f2tf(k4.y), f2tf(k4.z), f2tf(k4.w));
            float4 v4 = *(const float4*)&vg[r * Dn + c];
            *(float4*)&Vs[r * LKV + c] =
                make_float4(f2tf(v4.x), f2tf(v4.y), f2tf(v4.z), f2tf(v4.w));
        }
        __syncthreads();

        // S = Q @ K^T   (B operand = K^T -> element [k=d][n=kv] = Kn[kv][d])
        float s[8][4] = {};
#pragma unroll
        for (int ks = 0; ks < 8; ks++) {
            uint32_t bf[8][2];
#pragma unroll
            for (int nt = 0; nt < 8; nt++) {
                bf[nt][0] = __float_as_uint(Kn[(nt * 8 + g) * LKV + ks * 8 + q]);
                bf[nt][1] = __float_as_uint(Kn[(nt * 8 + g) * LKV + ks * 8 + q + 4]);
            }
#pragma unroll
            for (int nt = 0; nt < 8; nt++)
                mma8(s[nt], aQ[ks], bf[nt], s[nt]);
        }

        // Causal mask (only the diagonal tile needs it; local row vs local col)
        if (j == qt) {
            const int lr0 = w * 16 + g;
            const int lr1 = lr0 + 8;
#pragma unroll
            for (int nt = 0; nt < 8; nt++) {
                const int lc = nt * 8 + 2 * q;
                if (lc > lr0) s[nt][0] = -INFINITY;
                if (lc + 1 > lr0) s[nt][1] = -INFINITY;
                if (lc > lr1) s[nt][2] = -INFINITY;
                if (lc + 1 > lr1) s[nt][3] = -INFINITY;
            }
        }

        // Online softmax, registers + quad shuffles (logits are log2-scaled)
#pragma unroll
        for (int r = 0; r < 2; r++) {
            float mx = mrow[r];
#pragma unroll
            for (int nt = 0; nt < 8; nt++)
                mx = fmaxf(mx, fmaxf(s[nt][2 * r], s[nt][2 * r + 1]));
            mx = fmaxf(mx, __shfl_xor_sync(0xffffffffu, mx, 1));
            mx = fmaxf(mx, __shfl_xor_sync(0xffffffffu, mx, 2));
            const float alpha = ex2(mrow[r] - mx);
            float sum = 0.0f;
#pragma unroll
            for (int nt = 0; nt < 8; nt++) {
                const float p0 = ex2(s[nt][2 * r] - mx);
                const float p1 = ex2(s[nt][2 * r + 1] - mx);
                s[nt][2 * r] = p0;
                s[nt][2 * r + 1] = p1;
                sum += p0 + p1;
                o[nt][2 * r] *= alpha;
                o[nt][2 * r + 1] *= alpha;
            }
            sum += __shfl_xor_sync(0xffffffffu, sum, 1);
            sum += __shfl_xor_sync(0xffffffffu, sum, 2);
            lrow[r] = lrow[r] * alpha + sum;
            mrow[r] = mx;
        }

        // P: C-layout regs -> per-warp smem -> A-layout frags
#pragma unroll
        for (int nt = 0; nt < 8; nt++) {
            *(float2*)&Pme[g * LKV + nt * 8 + 2 * q] =
                make_float2(f2tf(s[nt][0]), f2tf(s[nt][1]));
            *(float2*)&Pme[(g + 8) * LKV + nt * 8 + 2 * q] =
                make_float2(f2tf(s[nt][2]), f2tf(s[nt][3]));
        }
        __syncwarp();

        // O += P @ V   (B operand = Vs[kv][d], k=kv, n=d)
#pragma unroll
        for (int ks = 0; ks < 8; ks++) {
            uint32_t aP[4];
            aP[0] = __float_as_uint(Pme[g * LKV + ks * 8 + q]);
            aP[1] = __float_as_uint(Pme[(g + 8) * LKV + ks * 8 + q]);
            aP[2] = __float_as_uint(Pme[g * LKV + ks * 8 + q + 4]);
            aP[3] = __float_as_uint(Pme[(g + 8) * LKV + ks * 8 + q + 4]);
            uint32_t bf[8][2];
#pragma unroll
            for (int nt = 0; nt < 8; nt++) {
                bf[nt][0] = __float_as_uint(Vs[(ks * 8 + q) * LKV + nt * 8 + g]);
                bf[nt][1] = __float_as_uint(Vs[(ks * 8 + q + 4) * LKV + nt * 8 + g]);
            }
#pragma unroll
            for (int nt = 0; nt < 8; nt++)
                mma8(o[nt], aP, bf[nt], o[nt]);
        }
    }

    // Normalize + write to g_y [B,T,C] at C-col h*64+d
    const float inv0 = 1.0f / lrow[0];
    const float inv1 = 1.0f / lrow[1];
    float* yg = g_y + ((size_t)b * Tn + qt * 64 + w * 16) * Cn + h * Dn;
#pragma unroll
    for (int nt = 0; nt < 8; nt++) {
        *(float2*)&yg[(size_t)g * Cn + nt * 8 + 2 * q] =
            make_float2(o[nt][0] * inv0, o[nt][1] * inv0);
        *(float2*)&yg[(size_t)(g + 8) * Cn + nt * 8 + 2 * q] =
            make_float2(o[nt][2] * inv1, o[nt][3] * inv1);
    }
}

// ---------------------------------------------------------------------------
extern "C" void kernel_launch(void* const* d_in, const int* in_sizes, int n_in,
                              void* d_out, int out_size) {
    const float* x      = (const float*)d_in[0];
    const float* w_qkv  = (const float*)d_in[1];
    const float* b_qkv  = (const float*)d_in[2];
    const float* w_proj = (const float*)d_in[3];
    const float* b_proj = (const float*)d_in[4];
    float* out = (float*)d_out;

    cudaFuncSetAttribute(attn_tc,
                         cudaFuncAttributeMaxDynamicSharedMemorySize, ATTN_SMEM);

    tf32_gemm<0><<<dim3(C3 / 128, NT / 128), 256>>>(x, w_qkv, b_qkv, nullptr, C3);
    attn_tc<<<dim3(Tn / 64, Bn * Hn), 128, ATTN_SMEM>>>();
    tf32_gemm<1><<<dim3(Cn / 128, NT / 128), 256>>>(nullptr, w_proj, b_proj, out, Cn);
}